// round 13
// baseline (speedup 1.0000x reference)
#include <cuda_runtime.h>
#include <math.h>

#define Bb 4
#define Ss 1024
#define Ee 256
#define Hh 8
#define Dd 32
#define TOK (Bb*Ss)
#define QB 32
#define RS 768          // QKV row stride (only Q region consumed now)
#define CT 128          // attention col tile
#define TP 1032         // padded T row
#define K2ST 36         // K-tile smem stride (uint2)
#define VT2ST 132       // transposed V-tile stride (uint2)
#define QE2 36          // Qe stride in uint2 (pre-split hi/lo)
#define REDW 1056       // 32*33 per-warp reduction slab
#define WN 896          // fused qkv+mlp1 output width
#define GST 20          // GEMM smem tile stride (uint2 units)
#define BUFF 9216       // BUF floats: max(128*36*2, 32*132*2, 8*1056)

// ---------------- scratch ----------------
__device__ float g_QKV[TOK*RS];     // only Q cols (0..255) written/used
__device__ float g_H[TOK*(Ee/2)];
__device__ uint2 g_x2[TOK*Ee];      // pre-split x
__device__ uint2 g_Wt2[WN*Ee];      // pre-split fused weights, transposed [n][k]
__device__ uint2 g_Wot2[Ee*Ee];     // pre-split W_out, transposed [n][k]
__device__ uint2 g_A2[TOK*Ee];      // pre-split attention output
__device__ uint2 g_K2[TOK*256];     // pre-split K: [token][h*32+d]
__device__ uint2 g_Vt2[Bb*256*Ss];  // pre-split transposed V: [(b*256 + h*32+d)][s]

// ---------------- tf32 helpers ----------------
__device__ __forceinline__ void tf32split(float x, unsigned &hi, unsigned &lo) {
    unsigned h; asm("cvt.rna.tf32.f32 %0, %1;" : "=r"(h) : "f"(x));
    float r = x - __uint_as_float(h);
    unsigned l; asm("cvt.rna.tf32.f32 %0, %1;" : "=r"(l) : "f"(r));
    hi = h; lo = l;
}

__device__ __forceinline__ void mma_tf32(float* d, const unsigned* a, unsigned b0, unsigned b1) {
    asm volatile("mma.sync.aligned.m16n8k8.row.col.f32.tf32.tf32.f32 "
        "{%0,%1,%2,%3},{%4,%5,%6,%7},{%8,%9},{%0,%1,%2,%3};"
        : "+f"(d[0]), "+f"(d[1]), "+f"(d[2]), "+f"(d[3])
        : "r"(a[0]), "r"(a[1]), "r"(a[2]), "r"(a[3]), "r"(b0), "r"(b1));
}

// ---------------- split kernels ----------------
__global__ __launch_bounds__(256)
void split_x_kernel(const float* __restrict__ x, uint2* __restrict__ gx)
{
    int i = blockIdx.x * 256 + threadIdx.x;
    unsigned h, l; tf32split(x[i], h, l);
    gx[i] = make_uint2(h, l);
}

__global__ __launch_bounds__(256)
void split_w_kernel(const float* __restrict__ Wq, const float* __restrict__ Wk,
                    const float* __restrict__ Wv, const float* __restrict__ W1,
                    const float* __restrict__ Wo,
                    uint2* __restrict__ gWt, uint2* __restrict__ gWot)
{
    int n = blockIdx.x;
    int k = threadIdx.x;
    float v;
    if      (n < 256) v = Wq[k*256 + n];
    else if (n < 512) v = Wk[k*256 + (n - 256)];
    else if (n < 768) v = Wv[k*256 + (n - 512)];
    else              v = W1[k*128 + (n - 768)];
    unsigned h, l; tf32split(v, h, l);
    gWt[n*256 + k] = make_uint2(h, l);
    if (n < 256) {
        tf32split(Wo[k*256 + n], h, l);
        gWot[n*256 + k] = make_uint2(h, l);
    }
}

// ---------------- pre-split tf32 MMA GEMM (64x64 tile, K=256) ----------------
// EPI 0: qkv_mlp epilogue: Q fp32 -> QKV; K split -> g_K2; V split+transposed -> g_Vt2;
//        MLP1 bias+gelu -> Hout
// EPI 1: out-proj epilogue (bias -> Cout, N=256)
template<int EPI>
__global__ __launch_bounds__(256)
void mma_gemm2(const uint2* __restrict__ A2, const uint2* __restrict__ B2t,
               const float* __restrict__ b1, const float* __restrict__ bo,
               float* __restrict__ QKV, float* __restrict__ Hout,
               uint2* __restrict__ K2, uint2* __restrict__ Vt2,
               float* __restrict__ Cout)
{
    __shared__ uint2 As2[64*GST];
    __shared__ uint2 Bs2[64*GST];
    const int tid = threadIdx.x;
    const int lane = tid & 31;
    const int w = tid >> 5;
    const int g = lane >> 2, td = lane & 3;
    const int wm = (w & 3) * 16, wn = (w >> 2) * 32;
    const int m0 = blockIdx.y * 64;
    const int n0 = blockIdx.x * 64;

    const int row = tid >> 2;
    const int c4  = (tid & 3) * 4;

    const uint2* gA = A2  + (size_t)(m0 + row) * 256 + c4;
    const uint2* gB = B2t + (size_t)(n0 + row) * 256 + c4;

    float acc[4][4];
    #pragma unroll
    for (int ng = 0; ng < 4; ++ng)
        #pragma unroll
        for (int r = 0; r < 4; ++r) acc[ng][r] = 0.f;

    uint4 ap0 = *(const uint4*)(gA);
    uint4 ap1 = *(const uint4*)(gA + 2);
    uint4 bp0 = *(const uint4*)(gB);
    uint4 bp1 = *(const uint4*)(gB + 2);

    for (int k0 = 0; k0 < 256; k0 += 16) {
        *(uint4*)&As2[row*GST + c4]     = ap0;
        *(uint4*)&As2[row*GST + c4 + 2] = ap1;
        *(uint4*)&Bs2[row*GST + c4]     = bp0;
        *(uint4*)&Bs2[row*GST + c4 + 2] = bp1;
        __syncthreads();
        if (k0 + 16 < 256) {
            ap0 = *(const uint4*)(gA + k0 + 16);
            ap1 = *(const uint4*)(gA + k0 + 18);
            bp0 = *(const uint4*)(gB + k0 + 16);
            bp1 = *(const uint4*)(gB + k0 + 18);
        }
        #pragma unroll
        for (int ks = 0; ks < 2; ++ks) {
            unsigned ah[4], al[4];
            {
                uint2 u0 = As2[(wm + g    )*GST + ks*8 + td];
                uint2 u1 = As2[(wm + g + 8)*GST + ks*8 + td];
                uint2 u2 = As2[(wm + g    )*GST + ks*8 + td + 4];
                uint2 u3 = As2[(wm + g + 8)*GST + ks*8 + td + 4];
                ah[0] = u0.x; al[0] = u0.y;
                ah[1] = u1.x; al[1] = u1.y;
                ah[2] = u2.x; al[2] = u2.y;
                ah[3] = u3.x; al[3] = u3.y;
            }
            #pragma unroll
            for (int ng = 0; ng < 4; ++ng) {
                uint2 ub0 = Bs2[(wn + ng*8 + g)*GST + ks*8 + td];
                uint2 ub1 = Bs2[(wn + ng*8 + g)*GST + ks*8 + td + 4];
                mma_tf32(acc[ng], ah, ub0.x, ub1.x);
                mma_tf32(acc[ng], ah, ub0.y, ub1.y);
                mma_tf32(acc[ng], al, ub0.x, ub1.x);
            }
        }
        __syncthreads();
    }

    #pragma unroll
    for (int ng = 0; ng < 4; ++ng) {
        int col = n0 + wn + ng*8 + 2*td;
        int r0  = m0 + wm + g;
        if (EPI == 0) {
            if (col < 256) {
                // Q: raw fp32 (consumed by attention Phase 0 blend)
                *(float2*)&QKV[(size_t)r0      *RS + col] = make_float2(acc[ng][0], acc[ng][1]);
                *(float2*)&QKV[(size_t)(r0 + 8)*RS + col] = make_float2(acc[ng][2], acc[ng][3]);
            } else if (col < 512) {
                // K: pre-split uint2, layout [token][h*32+d]
                unsigned h0,l0,h1,l1;
                tf32split(acc[ng][0], h0, l0); tf32split(acc[ng][1], h1, l1);
                *(uint4*)&K2[(size_t)r0*256 + (col - 256)] = make_uint4(h0,l0,h1,l1);
                tf32split(acc[ng][2], h0, l0); tf32split(acc[ng][3], h1, l1);
                *(uint4*)&K2[(size_t)(r0+8)*256 + (col - 256)] = make_uint4(h0,l0,h1,l1);
            } else if (col < 768) {
                // V: pre-split + transposed: [(b*256 + d_global)][s]
                int d0 = col - 512;
                unsigned hh, ll;
                {   int bb = r0 >> 10, s = r0 & 1023;
                    tf32split(acc[ng][0], hh, ll);
                    Vt2[((size_t)bb*256 + d0    )*1024 + s] = make_uint2(hh, ll);
                    tf32split(acc[ng][1], hh, ll);
                    Vt2[((size_t)bb*256 + d0 + 1)*1024 + s] = make_uint2(hh, ll); }
                {   int r1 = r0 + 8; int bb = r1 >> 10, s = r1 & 1023;
                    tf32split(acc[ng][2], hh, ll);
                    Vt2[((size_t)bb*256 + d0    )*1024 + s] = make_uint2(hh, ll);
                    tf32split(acc[ng][3], hh, ll);
                    Vt2[((size_t)bb*256 + d0 + 1)*1024 + s] = make_uint2(hh, ll); }
            } else {
                int n = col - 768;
                float bv0 = b1[n], bv1 = b1[n + 1];
                float v[4] = {acc[ng][0] + bv0, acc[ng][1] + bv1,
                              acc[ng][2] + bv0, acc[ng][3] + bv1};
                #pragma unroll
                for (int r = 0; r < 4; ++r)
                    v[r] = 0.5f * v[r] * (1.0f + erff(v[r] * 0.70710678118654752440f));
                *(float2*)&Hout[(size_t)r0      *128 + n] = make_float2(v[0], v[1]);
                *(float2*)&Hout[(size_t)(r0 + 8)*128 + n] = make_float2(v[2], v[3]);
            }
        } else {
            float bv0 = bo[col], bv1 = bo[col + 1];
            *(float2*)&Cout[(size_t)r0      *256 + col] = make_float2(acc[ng][0] + bv0, acc[ng][1] + bv1);
            *(float2*)&Cout[(size_t)(r0 + 8)*256 + col] = make_float2(acc[ng][2] + bv0, acc[ng][3] + bv1);
        }
    }
}

// ---------------- fused deformable attention (cvt-free tf32 MMA + fused MLP2) ----
__global__ __launch_bounds__(256, 1)
void attn_kernel(const float* __restrict__ Q, const uint2* __restrict__ K2,
                 const uint2* __restrict__ Vt2, const float* __restrict__ Hbuf,
                 const float* __restrict__ W2, const float* __restrict__ b2,
                 uint2* __restrict__ Aout2)
{
    extern __shared__ float sm[];
    float* T    = sm;                       // 32*TP
    float* BUF  = T + QB*TP;                // BUFF floats (K2s / Vt2s / reduction)
    uint2* Qe2  = (uint2*)(BUF + BUFF);     // 32*QE2 uint2
    float* offv = (float*)(Qe2 + QB*QE2);   // 64
    float* w2s  = offv + 64;                // 256
    float* wxs  = w2s + 256;                // 32
    float* rsum = wxs + QB;                 // 32
    int*   axs  = (int*)(rsum + QB);        // 32

    const int tid = threadIdx.x;
    const int nq  = Ss / QB;
    const int bh  = blockIdx.x / nq;
    const int q0  = (blockIdx.x % nq) * QB;
    const int b   = bh / Hh;
    const int h   = bh % Hh;
    const float scale = 0.17677669529663689f;

    const float* Qb  = Q  + (size_t)b*Ss*RS + h*Dd;
    const uint2* Kb2 = K2 + (size_t)(b*Ss)*256 + h*Dd;
    const uint2* Vtb2= Vt2 + ((size_t)b*256 + h*Dd)*1024;

    const int lane = tid & 31;
    const int w    = tid >> 5;
    const int g    = lane >> 2;
    const int td   = lane & 3;
    const int wm16 = (w >> 2) * 16;   // phase-1 m-block
    const int wn4  = (w & 3) * 32;    // phase-1 n-offset

    // ---- Phase 0a: fused MLP2 -> per-query offsets for this head ----
    {
        int k2 = tid >> 1, which2 = tid & 1;
        w2s[tid] = W2[k2*16 + 2*h + which2];
        __syncthreads();
        int group = tid >> 2, sub = tid & 3;
        int q = group >> 1, which = group & 1;
        const float* Hrow = Hbuf + (size_t)(b*Ss + q0 + q)*128 + sub*32;
        float s = 0.f;
        #pragma unroll
        for (int kk = 0; kk < 32; kk += 4) {
            float4 hv = *(const float4*)&Hrow[kk];
            int kb = (sub*32 + kk)*2 + which;
            s += hv.x * w2s[kb] + hv.y * w2s[kb + 2] + hv.z * w2s[kb + 4] + hv.w * w2s[kb + 6];
        }
        s += __shfl_xor_sync(0xffffffffu, s, 1);
        s += __shfl_xor_sync(0xffffffffu, s, 2);
        if (sub == 0) offv[q*2 + which] = s + b2[2*h + which];
    }
    __syncthreads();

    // ---- Phase 0b: Qeff (row-blended, pre-scaled), split hi/lo into smem ----
    {
        const int d = tid & 31;
        const int qq = tid >> 5;
        #pragma unroll
        for (int it = 0; it < 4; ++it) {
            int q = qq + it*8;
            int i = q0 + q;
            float ox = offv[q*2 + 0];
            float oy = offv[q*2 + 1];
            float fy = floorf(oy);
            float wy = oy - fy;
            int y0 = i + (int)fy, y1 = y0 + 1;
            float qv = 0.f;
            if (y0 >= 0 && y0 < Ss) qv += (1.f - wy) * Qb[(size_t)y0*RS + d];
            if (y1 >= 0 && y1 < Ss) qv += wy * Qb[(size_t)y1*RS + d];
            unsigned hh, ll;
            tf32split(qv * scale, hh, ll);
            Qe2[q*QE2 + d] = make_uint2(hh, ll);
            if (d == 0) { float fx = floorf(ox); wxs[q] = ox - fx; axs[q] = (int)fx; }
        }
    }
    __syncthreads();

    // ---- Phase 1: T = Qe . K^T (pure LDS+MMA; CT=128, 8 tiles) ----
    {
        uint2* K2s = (uint2*)BUF;
        uint4 pre[8];
        #pragma unroll
        for (int l = 0; l < 8; ++l) {
            int idx = tid + l*256;
            int c = idx >> 4, t = idx & 15;
            pre[l] = *(const uint4*)&Kb2[(size_t)c*256 + t*2];
        }
        for (int ct = 0; ct < Ss/CT; ++ct) {
            #pragma unroll
            for (int l = 0; l < 8; ++l) {
                int idx = tid + l*256;
                int c = idx >> 4, t = idx & 15;
                *(uint4*)&K2s[c*K2ST + t*2] = pre[l];
            }
            __syncthreads();
            if (ct + 1 < Ss/CT) {
                #pragma unroll
                for (int l = 0; l < 8; ++l) {
                    int idx = tid + l*256;
                    int c = idx >> 4, t = idx & 15;
                    pre[l] = *(const uint4*)&Kb2[(size_t)((ct+1)*CT + c)*256 + t*2];
                }
            }
            float acc[4][4];
            #pragma unroll
            for (int ng = 0; ng < 4; ++ng)
                #pragma unroll
                for (int r = 0; r < 4; ++r) acc[ng][r] = 0.f;

            #pragma unroll
            for (int ks = 0; ks < 4; ++ks) {
                unsigned ah[4], al[4];
                {
                    uint2 u0 = Qe2[(wm16 + g    )*QE2 + ks*8 + td];
                    uint2 u1 = Qe2[(wm16 + g + 8)*QE2 + ks*8 + td];
                    uint2 u2 = Qe2[(wm16 + g    )*QE2 + ks*8 + td + 4];
                    uint2 u3 = Qe2[(wm16 + g + 8)*QE2 + ks*8 + td + 4];
                    ah[0] = u0.x; al[0] = u0.y;
                    ah[1] = u1.x; al[1] = u1.y;
                    ah[2] = u2.x; al[2] = u2.y;
                    ah[3] = u3.x; al[3] = u3.y;
                }
                #pragma unroll
                for (int ng = 0; ng < 4; ++ng) {
                    uint2 ub0 = K2s[(wn4 + ng*8 + g)*K2ST + ks*8 + td];
                    uint2 ub1 = K2s[(wn4 + ng*8 + g)*K2ST + ks*8 + td + 4];
                    mma_tf32(acc[ng], ah, ub0.x, ub1.x);
                    mma_tf32(acc[ng], ah, ub0.y, ub1.y);
                    mma_tf32(acc[ng], al, ub0.x, ub1.x);
                }
            }
            #pragma unroll
            for (int ng = 0; ng < 4; ++ng) {
                int col = ct*CT + wn4 + ng*8 + 2*td;
                *(float2*)&T[(wm16 + g    )*TP + col] = make_float2(acc[ng][0], acc[ng][1]);
                *(float2*)&T[(wm16 + g + 8)*TP + col] = make_float2(acc[ng][2], acc[ng][3]);
            }
            __syncthreads();
        }
    }

    // ---- Phase 2: shift/blend + softmax; tf32-exact probs ----
    {
        #pragma unroll
        for (int it = 0; it < 4; ++it) {
            int q = w + it*8;
            float wx = wxs[q];
            int ax = axs[q];
            float* Tq = T + q*TP;
            float dv[32];
            float m = -1e30f;
            #pragma unroll
            for (int jj = 0; jj < 32; ++jj) {
                int j = lane + jj*32;
                int c0 = j + ax, c1 = c0 + 1;
                float t0 = (c0 >= 0 && c0 < Ss) ? Tq[c0] : 0.f;
                float t1 = (c1 >= 0 && c1 < Ss) ? Tq[c1] : 0.f;
                float v = (1.f - wx)*t0 + wx*t1;
                dv[jj] = v;
                m = fmaxf(m, v);
            }
            #pragma unroll
            for (int o = 16; o; o >>= 1) m = fmaxf(m, __shfl_xor_sync(0xffffffffu, m, o));
            float s = 0.f;
            #pragma unroll
            for (int jj = 0; jj < 32; ++jj) {
                float e = __expf(dv[jj] - m);
                unsigned er; asm("cvt.rna.tf32.f32 %0, %1;" : "=r"(er) : "f"(e));
                float ef = __uint_as_float(er);
                dv[jj] = ef; s += ef;
            }
            #pragma unroll
            for (int o = 16; o; o >>= 1) s += __shfl_xor_sync(0xffffffffu, s, o);
            #pragma unroll
            for (int jj = 0; jj < 32; ++jj) Tq[lane + jj*32] = dv[jj];
            if (lane == 0) rsum[q] = s;
        }
    }
    __syncthreads();

    // ---- Phase 3: out = P.V (pure LDS+MMA; V pre-split+transposed; CT=128) ----
    {
        uint2* Vt2s = (uint2*)BUF;
        float acc[4][2][4];
        #pragma unroll
        for (int ng = 0; ng < 4; ++ng)
            #pragma unroll
            for (int m = 0; m < 2; ++m)
                #pragma unroll
                for (int r = 0; r < 4; ++r) acc[ng][m][r] = 0.f;

        uint4 pre[8];
        #pragma unroll
        for (int l = 0; l < 8; ++l) {
            int idx = tid + l*256;
            int d = idx >> 6, t = idx & 63;
            pre[l] = *(const uint4*)&Vtb2[(size_t)d*1024 + t*2];
        }
        for (int jt = 0; jt < Ss/CT; ++jt) {
            #pragma unroll
            for (int l = 0; l < 8; ++l) {
                int idx = tid + l*256;
                int d = idx >> 6, t = idx & 63;
                *(uint4*)&Vt2s[d*VT2ST + t*2] = pre[l];
            }
            __syncthreads();
            if (jt + 1 < Ss/CT) {
                #pragma unroll
                for (int l = 0; l < 8; ++l) {
                    int idx = tid + l*256;
                    int d = idx >> 6, t = idx & 63;
                    pre[l] = *(const uint4*)&Vtb2[(size_t)d*1024 + (jt+1)*CT + t*2];
                }
            }
            #pragma unroll
            for (int ks = 0; ks < 2; ++ks) {
                int cbase  = jt*CT + w*16 + ks*8;
                int clocal = w*16 + ks*8;
                unsigned ah[8];
                #pragma unroll
                for (int m = 0; m < 2; ++m) {
                    ah[m*4+0] = __float_as_uint(T[(m*16 + g    )*TP + cbase + td]);
                    ah[m*4+1] = __float_as_uint(T[(m*16 + g + 8)*TP + cbase + td]);
                    ah[m*4+2] = __float_as_uint(T[(m*16 + g    )*TP + cbase + td + 4]);
                    ah[m*4+3] = __float_as_uint(T[(m*16 + g + 8)*TP + cbase + td + 4]);
                }
                #pragma unroll
                for (int ng = 0; ng < 4; ++ng) {
                    uint2 ub0 = Vt2s[(ng*8 + g)*VT2ST + clocal + td];
                    uint2 ub1 = Vt2s[(ng*8 + g)*VT2ST + clocal + td + 4];
                    #pragma unroll
                    for (int m = 0; m < 2; ++m) {
                        mma_tf32(acc[ng][m], ah + m*4, ub0.x, ub1.x);
                        mma_tf32(acc[ng][m], ah + m*4, ub0.y, ub1.y);
                    }
                }
            }
            __syncthreads();
        }
        #pragma unroll
        for (int ng = 0; ng < 4; ++ng) {
            int dcol = ng*8 + 2*td;
            #pragma unroll
            for (int m = 0; m < 2; ++m) {
                int r0 = m*16 + g;
                BUF[w*REDW +  r0     *33 + dcol    ] = acc[ng][m][0];
                BUF[w*REDW +  r0     *33 + dcol + 1] = acc[ng][m][1];
                BUF[w*REDW + (r0 + 8)*33 + dcol    ] = acc[ng][m][2];
                BUF[w*REDW + (r0 + 8)*33 + dcol + 1] = acc[ng][m][3];
            }
        }
        __syncthreads();
        for (int r = tid; r < QB*Dd; r += 256) {
            int q = r >> 5, d = r & 31;
            float s = 0.f;
            #pragma unroll
            for (int wv = 0; wv < 8; ++wv) s += BUF[wv*REDW + q*33 + d];
            int i = q0 + q;
            unsigned hh, ll;
            tf32split(s / rsum[q], hh, ll);
            Aout2[((size_t)b*Ss + i)*Ee + h*Dd + d] = make_uint2(hh, ll);
        }
    }
}

// ---------------- host launch ----------------
extern "C" void kernel_launch(void* const* d_in, const int* in_sizes, int n_in,
                              void* d_out, int out_size)
{
    (void)in_sizes; (void)n_in; (void)out_size;
    const float* x      = (const float*)d_in[0];
    const float* Wq     = (const float*)d_in[1];
    const float* Wk     = (const float*)d_in[2];
    const float* Wv     = (const float*)d_in[3];
    const float* W_off1 = (const float*)d_in[4];
    const float* b_off1 = (const float*)d_in[5];
    const float* W_off2 = (const float*)d_in[6];
    const float* b_off2 = (const float*)d_in[7];
    const float* W_out  = (const float*)d_in[8];
    const float* b_out  = (const float*)d_in[9];
    float* out = (float*)d_out;

    float *gQKV, *gH;
    uint2 *gx2, *gWt2, *gWot2, *gA2, *gK2, *gVt2;
    cudaGetSymbolAddress((void**)&gQKV,  g_QKV);
    cudaGetSymbolAddress((void**)&gH,    g_H);
    cudaGetSymbolAddress((void**)&gx2,   g_x2);
    cudaGetSymbolAddress((void**)&gWt2,  g_Wt2);
    cudaGetSymbolAddress((void**)&gWot2, g_Wot2);
    cudaGetSymbolAddress((void**)&gA2,   g_A2);
    cudaGetSymbolAddress((void**)&gK2,   g_K2);
    cudaGetSymbolAddress((void**)&gVt2,  g_Vt2);

    const int attn_smem = (QB*TP + BUFF + QB*QE2*2 + 64 + 256 + 3*QB) * (int)sizeof(float);
    cudaFuncSetAttribute(attn_kernel, cudaFuncAttributeMaxDynamicSharedMemorySize, attn_smem);

    dim3 blk(256);

    split_x_kernel<<<TOK*Ee/256, blk>>>(x, gx2);
    split_w_kernel<<<WN, blk>>>(Wq, Wk, Wv, W_off1, W_out, gWt2, gWot2);

    mma_gemm2<0><<<dim3(WN/64, TOK/64), blk>>>(gx2, gWt2, b_off1, nullptr,
                                               gQKV, gH, gK2, gVt2, nullptr);
    attn_kernel<<<Bb*Hh*(Ss/QB), blk, attn_smem>>>(gQKV, gK2, gVt2, gH, W_off2, b_off2, gA2);
    mma_gemm2<1><<<dim3(Ee/64, TOK/64), blk>>>(gA2, gWot2, nullptr, b_out,
                                               nullptr, nullptr, nullptr, nullptr, out);
}